// round 14
// baseline (speedup 1.0000x reference)
#include <cuda_runtime.h>
#include <cuda_fp16.h>
#include <math.h>
#include <stdint.h>

#define NNODE 16384
#define DCAT  1024
#define DHEAD 512
#define MAXE  (524288 + NNODE)

// ---------------- scratch (device globals; allocation-free contract) -------
__device__ __half g_xh[NNODE * DCAT];     // x @ W, fp16 (gather-friendly)
__device__ __half g_h16[NNODE * DCAT];    // aggregated + bias + relu, fp16
__device__ float  g_h128[NNODE * 128];
__device__ float  g_h64[NNODE * 64];
__device__ float4 g_hp[NNODE];            // (h3.x, h3.y, h3.z, sq)
__device__ float  g_asrc[NNODE * 2];
__device__ float  g_adst[NNODE * 2];
__device__ int    g_deg[NNODE];
__device__ int    g_cursor[NNODE];
__device__ int    g_rowptr[NNODE + 1];
__device__ int    g_csr_src[MAXE];
__device__ float2 g_csr_e[MAXE];          // raw exp(logit) per head (unnormalized)

// ---------------- tf32 helpers ---------------------------------------------
__device__ __forceinline__ uint32_t f2tf32(float f)
{
    uint32_t u;
    asm("cvt.rna.tf32.f32 %0, %1;" : "=r"(u) : "f"(f));
    return u;
}

__device__ __forceinline__ float4 cvt4(float4 v)
{
    float4 w;
    w.x = __uint_as_float(f2tf32(v.x));
    w.y = __uint_as_float(f2tf32(v.y));
    w.z = __uint_as_float(f2tf32(v.z));
    w.w = __uint_as_float(f2tf32(v.w));
    return w;
}

__device__ __forceinline__ void mma_tf32(float& c0, float& c1, float& c2, float& c3,
                                         uint32_t a0, uint32_t a1, uint32_t a2, uint32_t a3,
                                         uint32_t b0, uint32_t b1)
{
    asm volatile(
        "mma.sync.aligned.m16n8k8.row.col.f32.tf32.tf32.f32 "
        "{%0,%1,%2,%3}, {%4,%5,%6,%7}, {%8,%9}, {%0,%1,%2,%3};"
        : "+f"(c0), "+f"(c1), "+f"(c2), "+f"(c3)
        : "r"(a0), "r"(a1), "r"(a2), "r"(a3), "r"(b0), "r"(b1));
}

// ---------------- tf32 tensor-core GEMM (R5 mainloop, known-best) ----------
// C = A[M,K] @ B[K,N] (+bias)(+relu). BM=128, BN=64, BK=16, 256 threads =
// 8 warps (4 m x 2 n), 32x32 per warp. M%128==0, N%64==0, K%16==0.
// MODE selects A/C from device globals at compile time:
//   MODE 0: A = Aarg (input x, fp32), C = g_xh  (fp16)
//   MODE 1: A = g_h16 (fp16),         C = g_h128 (fp32)
//   MODE 2: A = g_h128 (fp32),        C = g_h64  (fp32)
template <int MODE, bool RELU>
__global__ __launch_bounds__(256)
void tf32gemm(int M, int N, int K,
              const float* __restrict__ Aarg, const float* __restrict__ B,
              const float* __restrict__ bias)
{
    const float* __restrict__ Af =
        (MODE == 0) ? Aarg : (const float*)g_h128;
    float* __restrict__ Cf =
        (MODE == 1) ? (float*)g_h128 : (float*)g_h64;

    constexpr int BM = 128, BN = 64, BK = 16;
    __shared__ float Am[BM][BK + 4];   // m-major, stride 20 (conflict-free frag LDS)
    __shared__ float Bs[BK][BN + 8];   // k-major, stride 72 (conflict-free frag LDS)

    const int tid   = threadIdx.x;
    const int lane  = tid & 31;
    const int wid   = tid >> 5;
    const int g     = lane >> 2;       // 0..7
    const int tig   = lane & 3;        // 0..3
    const int warpM = wid & 3;         // 0..3  (32 rows each)
    const int warpN = wid >> 2;        // 0..1  (32 cols each)
    const int m0    = blockIdx.y * BM;
    const int n0    = blockIdx.x * BN;

    float c[2][4][4];
#pragma unroll
    for (int mt = 0; mt < 2; mt++)
#pragma unroll
        for (int nt = 0; nt < 4; nt++)
#pragma unroll
            for (int i = 0; i < 4; i++) c[mt][nt][i] = 0.f;

    const int aRow = tid >> 2;         // 0..63
    const int aK   = (tid & 3) * 4;    // 0,4,8,12
    const int bK   = tid >> 4;         // 0..15
    const int bN   = (tid & 15) * 4;   // 0..60

    const float* Bptr = B + (size_t)bK * N + n0 + bN;

    for (int k0 = 0; k0 < K; k0 += BK) {
        if (MODE == 1) {
            // fp16 A (g_h16)
#pragma unroll
            for (int p = 0; p < 2; p++) {
                int r = p * 64 + aRow;
                uint2 v = *(const uint2*)(g_h16 + (size_t)(m0 + r) * K + k0 + aK);
                float2 p0 = __half22float2(*(__half2*)&v.x);
                float2 p1 = __half22float2(*(__half2*)&v.y);
                *(float4*)&Am[r][aK] = cvt4(make_float4(p0.x, p0.y, p1.x, p1.y));
            }
        } else {
            const float* Aptr = Af + (size_t)(m0 + aRow) * K + aK;
            *(float4*)&Am[aRow][aK]      = cvt4(*(const float4*)(Aptr + k0));
            *(float4*)&Am[64 + aRow][aK] = cvt4(*(const float4*)(Aptr + (size_t)64 * K + k0));
        }
        *(float4*)&Bs[bK][bN] = cvt4(*(const float4*)(Bptr + (size_t)k0 * N));
        __syncthreads();

#pragma unroll
        for (int kk = 0; kk < BK; kk += 8) {
            uint32_t a[2][4];
#pragma unroll
            for (int mt = 0; mt < 2; mt++) {
                int mm = warpM * 32 + mt * 16 + g;
                a[mt][0] = __float_as_uint(Am[mm][kk + tig]);
                a[mt][1] = __float_as_uint(Am[mm + 8][kk + tig]);
                a[mt][2] = __float_as_uint(Am[mm][kk + tig + 4]);
                a[mt][3] = __float_as_uint(Am[mm + 8][kk + tig + 4]);
            }
            uint32_t b[4][2];
#pragma unroll
            for (int nt = 0; nt < 4; nt++) {
                int nn = warpN * 32 + nt * 8 + g;
                b[nt][0] = __float_as_uint(Bs[kk + tig][nn]);
                b[nt][1] = __float_as_uint(Bs[kk + tig + 4][nn]);
            }
#pragma unroll
            for (int mt = 0; mt < 2; mt++)
#pragma unroll
                for (int nt = 0; nt < 4; nt++)
                    mma_tf32(c[mt][nt][0], c[mt][nt][1], c[mt][nt][2], c[mt][nt][3],
                             a[mt][0], a[mt][1], a[mt][2], a[mt][3],
                             b[nt][0], b[nt][1]);
        }
        __syncthreads();
    }

    // --- epilogue ---
#pragma unroll
    for (int mt = 0; mt < 2; mt++) {
        int r0 = m0 + warpM * 32 + mt * 16 + g;
#pragma unroll
        for (int nt = 0; nt < 4; nt++) {
            int cc = n0 + warpN * 32 + nt * 8 + 2 * tig;
            float b0 = 0.f, b1 = 0.f;
            if (bias) { b0 = bias[cc]; b1 = bias[cc + 1]; }
            float v00 = c[mt][nt][0] + b0, v01 = c[mt][nt][1] + b1;
            float v10 = c[mt][nt][2] + b0, v11 = c[mt][nt][3] + b1;
            if (RELU) {
                v00 = fmaxf(v00, 0.f); v01 = fmaxf(v01, 0.f);
                v10 = fmaxf(v10, 0.f); v11 = fmaxf(v11, 0.f);
            }
            if (MODE == 0) {
                *(__half2*)&g_xh[(size_t)r0 * N + cc]       = __floats2half2_rn(v00, v01);
                *(__half2*)&g_xh[(size_t)(r0 + 8) * N + cc] = __floats2half2_rn(v10, v11);
            } else {
                *(float2*)&Cf[(size_t)r0 * N + cc]       = make_float2(v00, v01);
                *(float2*)&Cf[(size_t)(r0 + 8) * N + cc] = make_float2(v10, v11);
            }
        }
    }
}

// ---------------- attention scores: a_src/a_dst [N,2], fp16 xh -------------
__global__ __launch_bounds__(128)
void attn_scores(const float* __restrict__ att_src,
                 const float* __restrict__ att_dst)
{
    int n = blockIdx.x;
    int w = threadIdx.x >> 5;      // 0..3
    int lane = threadIdx.x & 31;
    int h = w & 1;
    const __half2* row = (const __half2*)(g_xh + (size_t)n * DCAT + h * DHEAD);
    const float* att = ((w < 2) ? att_src : att_dst) + h * DHEAD;
    float s = 0.f;
    for (int i = lane; i < DHEAD / 2; i += 32) {
        float2 p = __half22float2(row[i]);
        s += p.x * att[2 * i] + p.y * att[2 * i + 1];
    }
#pragma unroll
    for (int o = 16; o > 0; o >>= 1) s += __shfl_down_sync(0xffffffffu, s, o);
    if (lane == 0) {
        float* out = (w < 2) ? g_asrc : g_adst;
        out[n * 2 + h] = s;
    }
}

// ---------------- zero init (deg) ------------------------------------------
__global__ void zero_init_kernel()
{
    int i = blockIdx.x * blockDim.x + threadIdx.x;
    if (i < NNODE) g_deg[i] = 0;
}

__device__ __forceinline__ float leaky(float x) { return x > 0.f ? x : 0.2f * x; }

// edge_index is int32; mask is a no-op on valid data but converts surprises
// into wrong values instead of device traps.
__device__ __forceinline__ void edge_sd(const int* __restrict__ ei, int e,
                                        int E, int& s, int& d)
{
    if (e < E) {
        s = ei[e] & (NNODE - 1);
        d = ei[E + e] & (NNODE - 1);
    } else {
        s = d = e - E;   // self-loop
    }
}

// ---------------- edge pass 1: degree histogram only -----------------------
__global__ __launch_bounds__(256)
void edge_pass1(const int* __restrict__ ei, int E, int Etot)
{
    int e = blockIdx.x * blockDim.x + threadIdx.x;
    if (e >= Etot) return;
    int s, d;
    edge_sd(ei, e, E, s, d);
    atomicAdd(&g_deg[d], 1);
}

// ---------------- exclusive scan of degrees --> rowptr, cursor -------------
__global__ __launch_bounds__(512)
void scan_kernel()
{
    __shared__ int sums[512];
    int t = threadIdx.x;
    int base = t * 32;
    int local[32];
    int s = 0;
#pragma unroll
    for (int i = 0; i < 32; i++) { local[i] = s; s += g_deg[base + i]; }
    sums[t] = s;
    __syncthreads();
    for (int off = 1; off < 512; off <<= 1) {
        int v = (t >= off) ? sums[t - off] : 0;
        __syncthreads();
        if (t >= off) sums[t] += v;
        __syncthreads();
    }
    int prefix = (t == 0) ? 0 : sums[t - 1];
#pragma unroll
    for (int i = 0; i < 32; i++) {
        g_rowptr[base + i] = prefix + local[i];
        g_cursor[base + i] = prefix + local[i];
    }
    if (t == 511) g_rowptr[NNODE] = sums[511];
}

// ---------------- edge pass 2: scatter CSR entries (src, exp) --------------
__global__ __launch_bounds__(256)
void edge_scatter(const int* __restrict__ ei, int E, int Etot)
{
    int e = blockIdx.x * blockDim.x + threadIdx.x;
    if (e >= Etot) return;
    int s, d;
    edge_sd(ei, e, E, s, d);
    int pos = atomicAdd(&g_cursor[d], 1);
    float2 ex;
    ex.x = expf(leaky(g_asrc[2 * s + 0] + g_adst[2 * d + 0]));
    ex.y = expf(leaky(g_asrc[2 * s + 1] + g_adst[2 * d + 1]));
    g_csr_src[pos] = s;
    g_csr_e[pos] = ex;
}

// ---------------- aggregation: MLP-4 gathers + fused softmax norm ----------
// 128 threads, 8 columns per thread; fp16 output.
__global__ __launch_bounds__(128)
void aggregate_kernel(const float* __restrict__ bias)
{
    int d = blockIdx.x;
    int c = threadIdx.x * 8;             // 0..1016
    bool head1 = (c >= DHEAD);
    int beg = g_rowptr[d], end = g_rowptr[d + 1];
    float acc[8];
#pragma unroll
    for (int k = 0; k < 8; k++) acc[k] = 0.f;
    float z = 0.f;                       // per-head softmax denominator

    const __half* xh = g_xh;
    int i = beg;
    for (; i + 4 <= end; i += 4) {
        int s0 = g_csr_src[i + 0], s1 = g_csr_src[i + 1];
        int s2 = g_csr_src[i + 2], s3 = g_csr_src[i + 3];
        float2 e0 = g_csr_e[i + 0], e1 = g_csr_e[i + 1];
        float2 e2 = g_csr_e[i + 2], e3 = g_csr_e[i + 3];
        uint4 v0 = *(const uint4*)(xh + (size_t)s0 * DCAT + c);
        uint4 v1 = *(const uint4*)(xh + (size_t)s1 * DCAT + c);
        uint4 v2 = *(const uint4*)(xh + (size_t)s2 * DCAT + c);
        uint4 v3 = *(const uint4*)(xh + (size_t)s3 * DCAT + c);
        float a0 = head1 ? e0.y : e0.x;
        float a1 = head1 ? e1.y : e1.x;
        float a2 = head1 ? e2.y : e2.x;
        float a3 = head1 ? e3.y : e3.x;
        z += (a0 + a1) + (a2 + a3);
#pragma unroll
        for (int q = 0; q < 4; q++) {
            uint32_t u0 = (&v0.x)[q], u1 = (&v1.x)[q], u2 = (&v2.x)[q], u3 = (&v3.x)[q];
            float2 p0 = __half22float2(*(__half2*)&u0);
            float2 p1 = __half22float2(*(__half2*)&u1);
            float2 p2 = __half22float2(*(__half2*)&u2);
            float2 p3 = __half22float2(*(__half2*)&u3);
            acc[2 * q + 0] = fmaf(a0, p0.x, fmaf(a1, p1.x, fmaf(a2, p2.x, fmaf(a3, p3.x, acc[2 * q + 0]))));
            acc[2 * q + 1] = fmaf(a0, p0.y, fmaf(a1, p1.y, fmaf(a2, p2.y, fmaf(a3, p3.y, acc[2 * q + 1]))));
        }
    }
    for (; i < end; i++) {
        int s = g_csr_src[i];
        float2 e = g_csr_e[i];
        float a = head1 ? e.y : e.x;
        z += a;
        uint4 v = *(const uint4*)(xh + (size_t)s * DCAT + c);
#pragma unroll
        for (int q = 0; q < 4; q++) {
            uint32_t u = (&v.x)[q];
            float2 p = __half22float2(*(__half2*)&u);
            acc[2 * q + 0] = fmaf(a, p.x, acc[2 * q + 0]);
            acc[2 * q + 1] = fmaf(a, p.y, acc[2 * q + 1]);
        }
    }

    float inv = 1.f / fmaxf(z, 1e-16f);
    float4 b0 = *(const float4*)(bias + c);
    float4 b1 = *(const float4*)(bias + c + 4);
    float r0 = fmaxf(fmaf(acc[0], inv, b0.x), 0.f);
    float r1 = fmaxf(fmaf(acc[1], inv, b0.y), 0.f);
    float r2 = fmaxf(fmaf(acc[2], inv, b0.z), 0.f);
    float r3 = fmaxf(fmaf(acc[3], inv, b0.w), 0.f);
    float r4 = fmaxf(fmaf(acc[4], inv, b1.x), 0.f);
    float r5 = fmaxf(fmaf(acc[5], inv, b1.y), 0.f);
    float r6 = fmaxf(fmaf(acc[6], inv, b1.z), 0.f);
    float r7 = fmaxf(fmaf(acc[7], inv, b1.w), 0.f);
    uint4 o;
    *(__half2*)&o.x = __floats2half2_rn(r0, r1);
    *(__half2*)&o.y = __floats2half2_rn(r2, r3);
    *(__half2*)&o.z = __floats2half2_rn(r4, r5);
    *(__half2*)&o.w = __floats2half2_rn(r6, r7);
    *(uint4*)(g_h16 + (size_t)d * DCAT + c) = o;
}

// ---------------- head: h3 = h64 @ W2 + b2, plus sq ------------------------
__global__ __launch_bounds__(256)
void head_kernel(const float* __restrict__ W2, const float* __restrict__ b2)
{
    int n = blockIdx.x * blockDim.x + threadIdx.x;
    if (n >= NNODE) return;
    float a0 = b2[0], a1 = b2[1], a2 = b2[2];
    const float* row = g_h64 + (size_t)n * 64;
#pragma unroll 8
    for (int k = 0; k < 64; k++) {
        float v = row[k];
        a0 = fmaf(v, W2[k * 3 + 0], a0);
        a1 = fmaf(v, W2[k * 3 + 1], a1);
        a2 = fmaf(v, W2[k * 3 + 2], a2);
    }
    float sq = fmaf(a2, a2, fmaf(a1, a1, a0 * a0));
    g_hp[n] = make_float4(a0, a1, a2, sq);
}

// ---------------- cdist: out[i][j] = ||h_i - h_j||, 4 j per thread ---------
__global__ __launch_bounds__(256)
void cdist_kernel(float* __restrict__ out)
{
    int j = (blockIdx.x * 256 + threadIdx.x) * 4;    // 0..16380
    int i = blockIdx.y;
    float4 hi = g_hp[i];
    float4 r;
    // dot uses the exact fmaf chain used for sq => diagonal is exactly 0
    {
        float4 hj = g_hp[j + 0];
        float dot = fmaf(hi.z, hj.z, fmaf(hi.y, hj.y, hi.x * hj.x));
        float d2 = fmaxf((hi.w + hj.w) - 2.f * dot, 0.f);
        r.x = (d2 > 0.f) ? sqrtf(d2) : 0.f;
    }
    {
        float4 hj = g_hp[j + 1];
        float dot = fmaf(hi.z, hj.z, fmaf(hi.y, hj.y, hi.x * hj.x));
        float d2 = fmaxf((hi.w + hj.w) - 2.f * dot, 0.f);
        r.y = (d2 > 0.f) ? sqrtf(d2) : 0.f;
    }
    {
        float4 hj = g_hp[j + 2];
        float dot = fmaf(hi.z, hj.z, fmaf(hi.y, hj.y, hi.x * hj.x));
        float d2 = fmaxf((hi.w + hj.w) - 2.f * dot, 0.f);
        r.z = (d2 > 0.f) ? sqrtf(d2) : 0.f;
    }
    {
        float4 hj = g_hp[j + 3];
        float dot = fmaf(hi.z, hj.z, fmaf(hi.y, hj.y, hi.x * hj.x));
        float d2 = fmaxf((hi.w + hj.w) - 2.f * dot, 0.f);
        r.w = (d2 > 0.f) ? sqrtf(d2) : 0.f;
    }
    *(float4*)&out[(size_t)i * NNODE + j] = r;
}

// ---------------------------------------------------------------------------
extern "C" void kernel_launch(void* const* d_in, const int* in_sizes, int n_in,
                              void* d_out, int out_size)
{
    const float* x       = (const float*)d_in[0];
    const int*   ei      = (const int*)d_in[1];      // int32 (JAX default)
    const float* W       = (const float*)d_in[2];
    const float* att_src = (const float*)d_in[3];
    const float* att_dst = (const float*)d_in[4];
    const float* bias    = (const float*)d_in[5];
    const float* Wa      = (const float*)d_in[6];
    const float* ba      = (const float*)d_in[7];
    const float* W1      = (const float*)d_in[8];
    const float* b1      = (const float*)d_in[9];
    const float* W2      = (const float*)d_in[10];
    const float* b2      = (const float*)d_in[11];
    float* out = (float*)d_out;

    int E = in_sizes[1] / 2;
    int Etot = E + NNODE;

    // Launch order puts tf32gemm<0> at position 4 so the fixed ncu window
    // (which has been capturing launch #4 every round) profiles it.
    // zero/pass1/scan are independent of the GEMM, so this is dependency-safe.

    // 1) zero deg
    zero_init_kernel<<<(NNODE + 255) / 256, 256>>>();

    // 2) degree histogram
    edge_pass1<<<(Etot + 255) / 256, 256>>>(ei, E, Etot);

    // 3) scan degrees -> rowptr/cursor
    scan_kernel<<<1, 512>>>();

    // 4) xh = x @ W   [16384,1024] K=512  (tf32, fp16 output)
    tf32gemm<0, false><<<dim3(DCAT / 64, NNODE / 128), 256>>>(
        NNODE, DCAT, 512, x, W, nullptr);

    // 5) attention scores
    attn_scores<<<NNODE, 128>>>(att_src, att_dst);

    // 6) scatter CSR (src, exp)
    edge_scatter<<<(Etot + 255) / 256, 256>>>(ei, E, Etot);

    // 7) aggregate (MLP-4 gathers, fused softmax norm) + bias + relu -> h16
    aggregate_kernel<<<NNODE, 128>>>(bias);

    // 8) h128 = relu(h16 @ Wa + ba)   K=1024, N=128
    tf32gemm<1, true><<<dim3(2, NNODE / 128), 256>>>(
        NNODE, 128, DCAT, nullptr, Wa, ba);

    // 9) h64 = relu(h128 @ W1 + b1)  K=128, N=64
    tf32gemm<2, true><<<dim3(1, NNODE / 128), 256>>>(
        NNODE, 64, 128, nullptr, W1, b1);

    // 10) h3 + sq
    head_kernel<<<NNODE / 256, 256>>>(W2, b2);

    // 11) cdist (float4 stores)
    cdist_kernel<<<dim3(NNODE / 1024, NNODE), 256>>>(out);

    (void)n_in; (void)out_size;
}

// round 15
// speedup vs baseline: 1.0977x; 1.0977x over previous
#include <cuda_runtime.h>
#include <cuda_fp16.h>
#include <math.h>
#include <stdint.h>

#define NNODE 16384
#define DCAT  1024
#define DHEAD 512
#define MAXE  (524288 + NNODE)

// ---------------- scratch (device globals; allocation-free contract) -------
__device__ __half g_xh[NNODE * DCAT];     // x @ W, fp16 (gather-friendly)
__device__ __half g_h16[NNODE * DCAT];    // aggregated + bias + relu, fp16
__device__ float  g_h128[NNODE * 128];
__device__ float  g_h64[NNODE * 64];
__device__ float4 g_hp[NNODE];            // (h3.x, h3.y, h3.z, sq)
__device__ float  g_asrc[NNODE * 2];
__device__ float  g_adst[NNODE * 2];
__device__ int    g_deg[NNODE];
__device__ int    g_cursor[NNODE];
__device__ int    g_rowptr[NNODE + 1];
__device__ int    g_csr_src[MAXE];
__device__ float2 g_csr_e[MAXE];          // raw exp(logit) per head (unnormalized)

// ---------------- fp16 MMA helpers -----------------------------------------
__device__ __forceinline__ uint32_t h2pack(float lo, float hi)
{
    __half2 h = __floats2half2_rn(lo, hi);
    return *(uint32_t*)&h;
}

__device__ __forceinline__ void mma_f16(float& c0, float& c1, float& c2, float& c3,
                                        uint32_t a0, uint32_t a1, uint32_t a2, uint32_t a3,
                                        uint32_t b0, uint32_t b1)
{
    asm volatile(
        "mma.sync.aligned.m16n8k16.row.col.f32.f16.f16.f32 "
        "{%0,%1,%2,%3}, {%4,%5,%6,%7}, {%8,%9}, {%0,%1,%2,%3};"
        : "+f"(c0), "+f"(c1), "+f"(c2), "+f"(c3)
        : "r"(a0), "r"(a1), "r"(a2), "r"(a3), "r"(b0), "r"(b1));
}

// ---------------- fp16 tensor-core GEMM ------------------------------------
// C = A[M,K] @ B[K,N] (+bias)(+relu). BM=128, BN=64, BK=16, 256 threads =
// 8 warps (4 m x 2 n), 32x32 per warp, m16n8k16 f16 MMA with f32 accum.
// M%128==0, N%64==0, K%16==0.
// A smem: m-major halves, row stride 24 (conflict-free fragment LDS.32).
// B smem: k-pair interleaved Bs[k/2][2n + (k&1)], pair-row stride 144 halves
//         (conflict-free fragment LDS.32).
// MODE selects A/C from device globals at compile time:
//   MODE 0: A = Aarg (input x, fp32), C = g_xh  (fp16)
//   MODE 1: A = g_h16 (fp16),         C = g_h128 (fp32)
//   MODE 2: A = g_h128 (fp32),        C = g_h64  (fp32)
template <int MODE, bool RELU>
__global__ __launch_bounds__(256)
void f16gemm(int M, int N, int K,
             const float* __restrict__ Aarg, const float* __restrict__ B,
             const float* __restrict__ bias)
{
    const float* __restrict__ Af =
        (MODE == 0) ? Aarg : (const float*)g_h128;
    float* __restrict__ Cf =
        (MODE == 1) ? (float*)g_h128 : (float*)g_h64;

    constexpr int BM = 128, BN = 64, BK = 16;
    constexpr int SA = 24;               // halves per A smem row
    constexpr int SB = 144;              // halves per B smem k-pair row
    __shared__ __half Am[BM][SA];
    __shared__ __half Bs[BK / 2][SB];

    const int tid   = threadIdx.x;
    const int lane  = tid & 31;
    const int wid   = tid >> 5;
    const int g     = lane >> 2;       // 0..7
    const int tig   = lane & 3;        // 0..3
    const int warpM = wid & 3;         // 0..3  (32 rows each)
    const int warpN = wid >> 2;        // 0..1  (32 cols each)
    const int m0    = blockIdx.y * BM;
    const int n0    = blockIdx.x * BN;

    float c[2][4][4];
#pragma unroll
    for (int mt = 0; mt < 2; mt++)
#pragma unroll
        for (int nt = 0; nt < 4; nt++)
#pragma unroll
            for (int i = 0; i < 4; i++) c[mt][nt][i] = 0.f;

    const int aRow = tid >> 2;         // 0..63
    const int aK   = (tid & 3) * 4;    // 0,4,8,12 (halves)
    const int bP   = tid >> 5;         // 0..7   k-pair
    const int bQ   = tid & 31;         // 0..31  n-pair

    for (int k0 = 0; k0 < K; k0 += BK) {
        // ---- stage A (two 64-row passes) ----
        if (MODE == 1) {
#pragma unroll
            for (int p = 0; p < 2; p++) {
                int r = p * 64 + aRow;
                uint2 v = *(const uint2*)(g_h16 + (size_t)(m0 + r) * K + k0 + aK);
                *(uint2*)&Am[r][aK] = v;
            }
        } else {
#pragma unroll
            for (int p = 0; p < 2; p++) {
                int r = p * 64 + aRow;
                float4 v = *(const float4*)(Af + (size_t)(m0 + r) * K + k0 + aK);
                uint2 w;
                w.x = h2pack(v.x, v.y);
                w.y = h2pack(v.z, v.w);
                *(uint2*)&Am[r][aK] = w;
            }
        }
        // ---- stage B: k-pair interleaved ----
        {
            const float* brow = B + (size_t)(k0 + 2 * bP) * N + n0 + 2 * bQ;
            float2 v0 = *(const float2*)brow;        // k = 2p,   n = 2q,2q+1
            float2 v1 = *(const float2*)(brow + N);  // k = 2p+1
            uint2 w;
            w.x = h2pack(v0.x, v1.x);                // (k2p,n2q),(k2p+1,n2q)
            w.y = h2pack(v0.y, v1.y);
            *(uint2*)&Bs[bP][4 * bQ] = w;
        }
        __syncthreads();

        uint32_t a[2][4];
#pragma unroll
        for (int mt = 0; mt < 2; mt++) {
            int mm = warpM * 32 + mt * 16 + g;
            a[mt][0] = *(const uint32_t*)&Am[mm][2 * tig];
            a[mt][1] = *(const uint32_t*)&Am[mm + 8][2 * tig];
            a[mt][2] = *(const uint32_t*)&Am[mm][2 * tig + 8];
            a[mt][3] = *(const uint32_t*)&Am[mm + 8][2 * tig + 8];
        }
        uint32_t b[4][2];
#pragma unroll
        for (int nt = 0; nt < 4; nt++) {
            int nn = warpN * 32 + nt * 8 + g;
            b[nt][0] = *(const uint32_t*)&Bs[tig][2 * nn];
            b[nt][1] = *(const uint32_t*)&Bs[tig + 4][2 * nn];
        }
#pragma unroll
        for (int mt = 0; mt < 2; mt++)
#pragma unroll
            for (int nt = 0; nt < 4; nt++)
                mma_f16(c[mt][nt][0], c[mt][nt][1], c[mt][nt][2], c[mt][nt][3],
                        a[mt][0], a[mt][1], a[mt][2], a[mt][3],
                        b[nt][0], b[nt][1]);
        __syncthreads();
    }

    // --- epilogue: D fragment mapping identical to m16n8k8 ---
#pragma unroll
    for (int mt = 0; mt < 2; mt++) {
        int r0 = m0 + warpM * 32 + mt * 16 + g;
#pragma unroll
        for (int nt = 0; nt < 4; nt++) {
            int cc = n0 + warpN * 32 + nt * 8 + 2 * tig;
            float b0 = 0.f, b1 = 0.f;
            if (bias) { b0 = bias[cc]; b1 = bias[cc + 1]; }
            float v00 = c[mt][nt][0] + b0, v01 = c[mt][nt][1] + b1;
            float v10 = c[mt][nt][2] + b0, v11 = c[mt][nt][3] + b1;
            if (RELU) {
                v00 = fmaxf(v00, 0.f); v01 = fmaxf(v01, 0.f);
                v10 = fmaxf(v10, 0.f); v11 = fmaxf(v11, 0.f);
            }
            if (MODE == 0) {
                *(__half2*)&g_xh[(size_t)r0 * N + cc]       = __floats2half2_rn(v00, v01);
                *(__half2*)&g_xh[(size_t)(r0 + 8) * N + cc] = __floats2half2_rn(v10, v11);
            } else {
                *(float2*)&Cf[(size_t)r0 * N + cc]       = make_float2(v00, v01);
                *(float2*)&Cf[(size_t)(r0 + 8) * N + cc] = make_float2(v10, v11);
            }
        }
    }
}

// ---------------- attention scores: a_src/a_dst [N,2], fp16 xh -------------
__global__ __launch_bounds__(128)
void attn_scores(const float* __restrict__ att_src,
                 const float* __restrict__ att_dst)
{
    int n = blockIdx.x;
    int w = threadIdx.x >> 5;      // 0..3
    int lane = threadIdx.x & 31;
    int h = w & 1;
    const __half2* row = (const __half2*)(g_xh + (size_t)n * DCAT + h * DHEAD);
    const float* att = ((w < 2) ? att_src : att_dst) + h * DHEAD;
    float s = 0.f;
    for (int i = lane; i < DHEAD / 2; i += 32) {
        float2 p = __half22float2(row[i]);
        s += p.x * att[2 * i] + p.y * att[2 * i + 1];
    }
#pragma unroll
    for (int o = 16; o > 0; o >>= 1) s += __shfl_down_sync(0xffffffffu, s, o);
    if (lane == 0) {
        float* out = (w < 2) ? g_asrc : g_adst;
        out[n * 2 + h] = s;
    }
}

// ---------------- zero init (deg) ------------------------------------------
__global__ void zero_init_kernel()
{
    int i = blockIdx.x * blockDim.x + threadIdx.x;
    if (i < NNODE) g_deg[i] = 0;
}

__device__ __forceinline__ float leaky(float x) { return x > 0.f ? x : 0.2f * x; }

// edge_index is int32; mask is a no-op on valid data but converts surprises
// into wrong values instead of device traps.
__device__ __forceinline__ void edge_sd(const int* __restrict__ ei, int e,
                                        int E, int& s, int& d)
{
    if (e < E) {
        s = ei[e] & (NNODE - 1);
        d = ei[E + e] & (NNODE - 1);
    } else {
        s = d = e - E;   // self-loop
    }
}

// ---------------- edge pass 1: degree histogram only -----------------------
__global__ __launch_bounds__(256)
void edge_pass1(const int* __restrict__ ei, int E, int Etot)
{
    int e = blockIdx.x * blockDim.x + threadIdx.x;
    if (e >= Etot) return;
    int s, d;
    edge_sd(ei, e, E, s, d);
    atomicAdd(&g_deg[d], 1);
}

// ---------------- exclusive scan of degrees --> rowptr, cursor -------------
__global__ __launch_bounds__(512)
void scan_kernel()
{
    __shared__ int sums[512];
    int t = threadIdx.x;
    int base = t * 32;
    int local[32];
    int s = 0;
#pragma unroll
    for (int i = 0; i < 32; i++) { local[i] = s; s += g_deg[base + i]; }
    sums[t] = s;
    __syncthreads();
    for (int off = 1; off < 512; off <<= 1) {
        int v = (t >= off) ? sums[t - off] : 0;
        __syncthreads();
        if (t >= off) sums[t] += v;
        __syncthreads();
    }
    int prefix = (t == 0) ? 0 : sums[t - 1];
#pragma unroll
    for (int i = 0; i < 32; i++) {
        g_rowptr[base + i] = prefix + local[i];
        g_cursor[base + i] = prefix + local[i];
    }
    if (t == 511) g_rowptr[NNODE] = sums[511];
}

// ---------------- edge pass 2: scatter CSR entries (src, exp) --------------
__global__ __launch_bounds__(256)
void edge_scatter(const int* __restrict__ ei, int E, int Etot)
{
    int e = blockIdx.x * blockDim.x + threadIdx.x;
    if (e >= Etot) return;
    int s, d;
    edge_sd(ei, e, E, s, d);
    int pos = atomicAdd(&g_cursor[d], 1);
    float2 ex;
    ex.x = expf(leaky(g_asrc[2 * s + 0] + g_adst[2 * d + 0]));
    ex.y = expf(leaky(g_asrc[2 * s + 1] + g_adst[2 * d + 1]));
    g_csr_src[pos] = s;
    g_csr_e[pos] = ex;
}

// ---------------- aggregation: MLP-4 gathers + fused softmax norm ----------
// 128 threads, 8 columns per thread; fp16 output.
__global__ __launch_bounds__(128)
void aggregate_kernel(const float* __restrict__ bias)
{
    int d = blockIdx.x;
    int c = threadIdx.x * 8;             // 0..1016
    bool head1 = (c >= DHEAD);
    int beg = g_rowptr[d], end = g_rowptr[d + 1];
    float acc[8];
#pragma unroll
    for (int k = 0; k < 8; k++) acc[k] = 0.f;
    float z = 0.f;                       // per-head softmax denominator

    const __half* xh = g_xh;
    int i = beg;
    for (; i + 4 <= end; i += 4) {
        int s0 = g_csr_src[i + 0], s1 = g_csr_src[i + 1];
        int s2 = g_csr_src[i + 2], s3 = g_csr_src[i + 3];
        float2 e0 = g_csr_e[i + 0], e1 = g_csr_e[i + 1];
        float2 e2 = g_csr_e[i + 2], e3 = g_csr_e[i + 3];
        uint4 v0 = *(const uint4*)(xh + (size_t)s0 * DCAT + c);
        uint4 v1 = *(const uint4*)(xh + (size_t)s1 * DCAT + c);
        uint4 v2 = *(const uint4*)(xh + (size_t)s2 * DCAT + c);
        uint4 v3 = *(const uint4*)(xh + (size_t)s3 * DCAT + c);
        float a0 = head1 ? e0.y : e0.x;
        float a1 = head1 ? e1.y : e1.x;
        float a2 = head1 ? e2.y : e2.x;
        float a3 = head1 ? e3.y : e3.x;
        z += (a0 + a1) + (a2 + a3);
#pragma unroll
        for (int q = 0; q < 4; q++) {
            uint32_t u0 = (&v0.x)[q], u1 = (&v1.x)[q], u2 = (&v2.x)[q], u3 = (&v3.x)[q];
            float2 p0 = __half22float2(*(__half2*)&u0);
            float2 p1 = __half22float2(*(__half2*)&u1);
            float2 p2 = __half22float2(*(__half2*)&u2);
            float2 p3 = __half22float2(*(__half2*)&u3);
            acc[2 * q + 0] = fmaf(a0, p0.x, fmaf(a1, p1.x, fmaf(a2, p2.x, fmaf(a3, p3.x, acc[2 * q + 0]))));
            acc[2 * q + 1] = fmaf(a0, p0.y, fmaf(a1, p1.y, fmaf(a2, p2.y, fmaf(a3, p3.y, acc[2 * q + 1]))));
        }
    }
    for (; i < end; i++) {
        int s = g_csr_src[i];
        float2 e = g_csr_e[i];
        float a = head1 ? e.y : e.x;
        z += a;
        uint4 v = *(const uint4*)(xh + (size_t)s * DCAT + c);
#pragma unroll
        for (int q = 0; q < 4; q++) {
            uint32_t u = (&v.x)[q];
            float2 p = __half22float2(*(__half2*)&u);
            acc[2 * q + 0] = fmaf(a, p.x, acc[2 * q + 0]);
            acc[2 * q + 1] = fmaf(a, p.y, acc[2 * q + 1]);
        }
    }

    float inv = 1.f / fmaxf(z, 1e-16f);
    float4 b0 = *(const float4*)(bias + c);
    float4 b1 = *(const float4*)(bias + c + 4);
    float r0 = fmaxf(fmaf(acc[0], inv, b0.x), 0.f);
    float r1 = fmaxf(fmaf(acc[1], inv, b0.y), 0.f);
    float r2 = fmaxf(fmaf(acc[2], inv, b0.z), 0.f);
    float r3 = fmaxf(fmaf(acc[3], inv, b0.w), 0.f);
    float r4 = fmaxf(fmaf(acc[4], inv, b1.x), 0.f);
    float r5 = fmaxf(fmaf(acc[5], inv, b1.y), 0.f);
    float r6 = fmaxf(fmaf(acc[6], inv, b1.z), 0.f);
    float r7 = fmaxf(fmaf(acc[7], inv, b1.w), 0.f);
    uint4 o;
    *(__half2*)&o.x = __floats2half2_rn(r0, r1);
    *(__half2*)&o.y = __floats2half2_rn(r2, r3);
    *(__half2*)&o.z = __floats2half2_rn(r4, r5);
    *(__half2*)&o.w = __floats2half2_rn(r6, r7);
    *(uint4*)(g_h16 + (size_t)d * DCAT + c) = o;
}

// ---------------- head: h3 = h64 @ W2 + b2, plus sq ------------------------
__global__ __launch_bounds__(256)
void head_kernel(const float* __restrict__ W2, const float* __restrict__ b2)
{
    int n = blockIdx.x * blockDim.x + threadIdx.x;
    if (n >= NNODE) return;
    float a0 = b2[0], a1 = b2[1], a2 = b2[2];
    const float* row = g_h64 + (size_t)n * 64;
#pragma unroll 8
    for (int k = 0; k < 64; k++) {
        float v = row[k];
        a0 = fmaf(v, W2[k * 3 + 0], a0);
        a1 = fmaf(v, W2[k * 3 + 1], a1);
        a2 = fmaf(v, W2[k * 3 + 2], a2);
    }
    float sq = fmaf(a2, a2, fmaf(a1, a1, a0 * a0));
    g_hp[n] = make_float4(a0, a1, a2, sq);
}

// ---------------- cdist: out[i][j] = ||h_i - h_j||, 4 j per thread ---------
__global__ __launch_bounds__(256)
void cdist_kernel(float* __restrict__ out)
{
    int j = (blockIdx.x * 256 + threadIdx.x) * 4;    // 0..16380
    int i = blockIdx.y;
    float4 hi = g_hp[i];
    float4 r;
    // dot uses the exact fmaf chain used for sq => diagonal is exactly 0
    {
        float4 hj = g_hp[j + 0];
        float dot = fmaf(hi.z, hj.z, fmaf(hi.y, hj.y, hi.x * hj.x));
        float d2 = fmaxf((hi.w + hj.w) - 2.f * dot, 0.f);
        r.x = (d2 > 0.f) ? sqrtf(d2) : 0.f;
    }
    {
        float4 hj = g_hp[j + 1];
        float dot = fmaf(hi.z, hj.z, fmaf(hi.y, hj.y, hi.x * hj.x));
        float d2 = fmaxf((hi.w + hj.w) - 2.f * dot, 0.f);
        r.y = (d2 > 0.f) ? sqrtf(d2) : 0.f;
    }
    {
        float4 hj = g_hp[j + 2];
        float dot = fmaf(hi.z, hj.z, fmaf(hi.y, hj.y, hi.x * hj.x));
        float d2 = fmaxf((hi.w + hj.w) - 2.f * dot, 0.f);
        r.z = (d2 > 0.f) ? sqrtf(d2) : 0.f;
    }
    {
        float4 hj = g_hp[j + 3];
        float dot = fmaf(hi.z, hj.z, fmaf(hi.y, hj.y, hi.x * hj.x));
        float d2 = fmaxf((hi.w + hj.w) - 2.f * dot, 0.f);
        r.w = (d2 > 0.f) ? sqrtf(d2) : 0.f;
    }
    *(float4*)&out[(size_t)i * NNODE + j] = r;
}

// ---------------------------------------------------------------------------
extern "C" void kernel_launch(void* const* d_in, const int* in_sizes, int n_in,
                              void* d_out, int out_size)
{
    const float* x       = (const float*)d_in[0];
    const int*   ei      = (const int*)d_in[1];      // int32 (JAX default)
    const float* W       = (const float*)d_in[2];
    const float* att_src = (const float*)d_in[3];
    const float* att_dst = (const float*)d_in[4];
    const float* bias    = (const float*)d_in[5];
    const float* Wa      = (const float*)d_in[6];
    const float* ba      = (const float*)d_in[7];
    const float* W1      = (const float*)d_in[8];
    const float* b1      = (const float*)d_in[9];
    const float* W2      = (const float*)d_in[10];
    const float* b2      = (const float*)d_in[11];
    float* out = (float*)d_out;

    int E = in_sizes[1] / 2;
    int Etot = E + NNODE;

    // Launch order keeps the main GEMM at position 4 for the ncu window.

    // 1) zero deg
    zero_init_kernel<<<(NNODE + 255) / 256, 256>>>();

    // 2) degree histogram
    edge_pass1<<<(Etot + 255) / 256, 256>>>(ei, E, Etot);

    // 3) scan degrees -> rowptr/cursor
    scan_kernel<<<1, 512>>>();

    // 4) xh = x @ W   [16384,1024] K=512  (fp16 MMA, fp16 output)
    f16gemm<0, false><<<dim3(DCAT / 64, NNODE / 128), 256>>>(
        NNODE, DCAT, 512, x, W, nullptr);

    // 5) attention scores
    attn_scores<<<NNODE, 128>>>(att_src, att_dst);

    // 6) scatter CSR (src, exp)
    edge_scatter<<<(Etot + 255) / 256, 256>>>(ei, E, Etot);

    // 7) aggregate (MLP-4 gathers, fused softmax norm) + bias + relu -> h16
    aggregate_kernel<<<NNODE, 128>>>(bias);

    // 8) h128 = relu(h16 @ Wa + ba)   K=1024, N=128
    f16gemm<1, true><<<dim3(2, NNODE / 128), 256>>>(
        NNODE, 128, DCAT, nullptr, Wa, ba);

    // 9) h64 = relu(h128 @ W1 + b1)  K=128, N=64
    f16gemm<2, true><<<dim3(1, NNODE / 128), 256>>>(
        NNODE, 64, 128, nullptr, W1, b1);

    // 10) h3 + sq
    head_kernel<<<NNODE / 256, 256>>>(W2, b2);

    // 11) cdist (float4 stores)
    cdist_kernel<<<dim3(NNODE / 1024, NNODE), 256>>>(out);

    (void)n_in; (void)out_size;
}